// round 10
// baseline (speedup 1.0000x reference)
#include <cuda_runtime.h>
#include <cuda_bf16.h>
#include <math.h>
#include <stdint.h>

// Problem constants
#define Bc   8
#define Tc   2048
#define Cc   512
#define Hc   8
#define Nc   64
#define DMIX 32
#define DDEC 64
#define BT   (Bc*Tc)           // 16384
#define BTC  (BT*Cc)           // 8388608

// ---------------------------------------------------------------------------
// Scratch (static device globals; no allocation allowed)
// ---------------------------------------------------------------------------
__device__ float g_xx  [BTC];
__device__ float g_xxx [BTC];
__device__ float g_h   [BT*160];
__device__ float g_xw  [BTC];
__device__ float g_xk  [BTC];
__device__ float g_xv  [BTC];
__device__ float g_xr  [BTC];
__device__ float g_xg  [BTC];
__device__ float g_r   [BTC];
__device__ float g_k   [BTC];
__device__ float g_v   [BTC];
__device__ float g_gate[BTC];
__device__ float g_wp  [BT*DDEC];
__device__ float g_w   [BTC];
__device__ float g_y   [BTC];    // WKV partial (j-half 0)
__device__ float g_y2  [BTC];    // WKV partial (j-half 1)
__device__ float g_z   [BTC];
__device__ float g_w1t [256*512];   // W1^T padded 160->256 rows
__device__ float g_dw1t[128*512];   // dw1^T padded 64->128 rows
__device__ float g_dw2t[512*64];    // dw2^T [512][64]

// ---------------------------------------------------------------------------
// Elementwise: token shift + xxx = x + xx * maa_x
// ---------------------------------------------------------------------------
__global__ void ew_shift_mix(const float* __restrict__ x,
                             const float* __restrict__ maa_x,
                             float* __restrict__ xx, float* __restrict__ xxx)
{
    int idx = blockIdx.x * 256 + threadIdx.x;
    if (idx >= BTC) return;
    int c  = idx & (Cc - 1);
    int tg = idx >> 9;
    int tt = tg & (Tc - 1);
    float xi = x[idx];
    float xs = (tt > 0) ? x[idx - Cc] : 0.f;
    float xxv = xs - xi;
    xx[idx]  = xxv;
    xxx[idx] = fmaf(xxv, maa_x[c], xi);
}

// ---------------------------------------------------------------------------
// Weight transpose + zero-pad (tiny, once per call)
// ---------------------------------------------------------------------------
__global__ void transpose_pad(const float* __restrict__ W1,
                              const float* __restrict__ dw1,
                              const float* __restrict__ dw2,
                              float* __restrict__ w1t,
                              float* __restrict__ dw1t,
                              float* __restrict__ dw2t)
{
    int idx = blockIdx.x * 256 + threadIdx.x;
    if (idx < 256 * 512) {
        int n = idx >> 9, k = idx & 511;
        w1t[idx] = (n < 160) ? W1[k * 160 + n] : 0.f;
    } else if (idx < 256 * 512 + 128 * 512) {
        int j = idx - 256 * 512;
        int n = j >> 9, k = j & 511;
        dw1t[j] = (n < 64) ? dw1[k * 64 + n] : 0.f;
    } else if (idx < 256 * 512 + 128 * 512 + 512 * 64) {
        int j = idx - (256 * 512 + 128 * 512);
        int n = j >> 6, k = j & 63;
        dw2t[j] = dw2[k * 512 + n];
    }
}

// ---------------------------------------------------------------------------
// TF32 tensor-core GEMM: C[M,Nreal] = epi( A[M,K] @ W[Npad,K]^T )
//   cp.async 2-stage static-smem double buffer (40KB). cvt on fragment load.
//   epi: 0 none, 1 tanh, 2 silu, 3 exp(-exp(bias[n]+v))
// ---------------------------------------------------------------------------
__device__ __forceinline__ uint32_t f2tf32(float x)
{
    uint32_t u;
    asm("cvt.rna.tf32.f32 %0, %1;" : "=r"(u) : "f"(x));
    return u;
}

__device__ __forceinline__ void tf32_body(const float* __restrict__ A,
                                          const float* __restrict__ W,
                                          float* __restrict__ Cm,
                                          const float* __restrict__ bias,
                                          int M, int K, int Nreal, int ldc, int epi)
{
    __shared__ float As[2][128][20];
    __shared__ float Bs[2][128][20];

    int tid  = threadIdx.x;
    int warp = tid >> 5, lane = tid & 31;
    int wm = (warp >> 2) * 64;
    int wn = (warp & 3) * 32;
    int gid = lane >> 2, tig = lane & 3;
    int m0 = blockIdx.y * 128, n0 = blockIdx.x * 128;

    int lr = tid >> 1;
    int lq = (tid & 1) * 2;
    const float* Aptr = A + (size_t)(m0 + lr) * K;
    const float* Wptr = W + (size_t)(n0 + lr) * K;

    float acc[4][4][4];
#pragma unroll
    for (int mt = 0; mt < 4; mt++)
#pragma unroll
        for (int nt = 0; nt < 4; nt++)
#pragma unroll
            for (int d = 0; d < 4; d++) acc[mt][nt][d] = 0.f;

    auto stage = [&](int buf, int k0) {
#pragma unroll
        for (int i = 0; i < 2; i++) {
            int kq = (lq + i) * 4;
            uint32_t da = (uint32_t)__cvta_generic_to_shared(&As[buf][lr][kq]);
            asm volatile("cp.async.cg.shared.global [%0], [%1], 16;"
                         :: "r"(da), "l"(Aptr + k0 + kq));
            uint32_t db = (uint32_t)__cvta_generic_to_shared(&Bs[buf][lr][kq]);
            asm volatile("cp.async.cg.shared.global [%0], [%1], 16;"
                         :: "r"(db), "l"(Wptr + k0 + kq));
        }
        asm volatile("cp.async.commit_group;");
    };

    int ntiles = K >> 4;
    stage(0, 0);
    if (ntiles > 1) stage(1, 16); else asm volatile("cp.async.commit_group;");
    asm volatile("cp.async.wait_group 1;");
    __syncthreads();

    for (int i = 0; i < ntiles; i++) {
        int buf = i & 1;

#pragma unroll
        for (int ks = 0; ks < 2; ks++) {
            int kb = ks * 8;
            uint32_t afr[4][4];
#pragma unroll
            for (int mt = 0; mt < 4; mt++) {
                int m = wm + mt * 16;
                afr[mt][0] = f2tf32(As[buf][m + gid    ][kb + tig    ]);
                afr[mt][1] = f2tf32(As[buf][m + gid + 8][kb + tig    ]);
                afr[mt][2] = f2tf32(As[buf][m + gid    ][kb + tig + 4]);
                afr[mt][3] = f2tf32(As[buf][m + gid + 8][kb + tig + 4]);
            }
            uint32_t bfr[4][2];
#pragma unroll
            for (int nt = 0; nt < 4; nt++) {
                int n = wn + nt * 8;
                bfr[nt][0] = f2tf32(Bs[buf][n + gid][kb + tig    ]);
                bfr[nt][1] = f2tf32(Bs[buf][n + gid][kb + tig + 4]);
            }
#pragma unroll
            for (int mt = 0; mt < 4; mt++)
#pragma unroll
                for (int nt = 0; nt < 4; nt++) {
                    asm volatile(
                        "mma.sync.aligned.m16n8k8.row.col.f32.tf32.tf32.f32 "
                        "{%0,%1,%2,%3}, {%4,%5,%6,%7}, {%8,%9}, {%0,%1,%2,%3};"
                        : "+f"(acc[mt][nt][0]), "+f"(acc[mt][nt][1]),
                          "+f"(acc[mt][nt][2]), "+f"(acc[mt][nt][3])
                        : "r"(afr[mt][0]), "r"(afr[mt][1]),
                          "r"(afr[mt][2]), "r"(afr[mt][3]),
                          "r"(bfr[nt][0]), "r"(bfr[nt][1]));
                }
        }

        __syncthreads();
        if (i + 2 < ntiles) stage(buf, (i + 2) * 16);
        else                asm volatile("cp.async.commit_group;");
        asm volatile("cp.async.wait_group 1;");
        __syncthreads();
    }

#pragma unroll
    for (int mt = 0; mt < 4; mt++) {
        int m = m0 + wm + mt * 16 + gid;
#pragma unroll
        for (int nt = 0; nt < 4; nt++) {
            int gb = n0 + wn + nt * 8;
            if (gb >= Nreal) continue;
            int n = gb + 2 * tig;
            float v0 = acc[mt][nt][0], v1 = acc[mt][nt][1];
            float v2 = acc[mt][nt][2], v3 = acc[mt][nt][3];
            if (epi == 1) {
                v0 = tanhf(v0); v1 = tanhf(v1); v2 = tanhf(v2); v3 = tanhf(v3);
            } else if (epi == 2) {
                v0 = v0 / (1.f + expf(-v0));
                v1 = v1 / (1.f + expf(-v1));
                v2 = v2 / (1.f + expf(-v2));
                v3 = v3 / (1.f + expf(-v3));
            } else if (epi == 3) {
                float b0 = bias[n], b1 = bias[n + 1];
                v0 = expf(-expf(b0 + v0));
                v1 = expf(-expf(b1 + v1));
                v2 = expf(-expf(b0 + v2));
                v3 = expf(-expf(b1 + v3));
            }
            *reinterpret_cast<float2*>(&Cm[(size_t)m * ldc + n])       = make_float2(v0, v1);
            *reinterpret_cast<float2*>(&Cm[(size_t)(m + 8) * ldc + n]) = make_float2(v2, v3);
        }
    }
}

__global__ __launch_bounds__(256)
void tf32_gemm(const float* __restrict__ A, const float* __restrict__ W,
               float* __restrict__ C, const float* __restrict__ bias,
               int M, int K, int Nreal, int ldc, int epi)
{
    tf32_body(A, W, C, bias, M, K, Nreal, ldc, epi);
}

// 4 projections in one launch (blockIdx.z selects)
__global__ __launch_bounds__(256)
void proj4_kernel(const float* __restrict__ xr, const float* __restrict__ xk,
                  const float* __restrict__ xv, const float* __restrict__ xg,
                  const float* __restrict__ Wr, const float* __restrict__ Wk,
                  const float* __restrict__ Wv, const float* __restrict__ Wg,
                  float* __restrict__ r, float* __restrict__ k,
                  float* __restrict__ v, float* __restrict__ g)
{
    const float* A; const float* W; float* C; int epi = 0;
    int z = blockIdx.z;
    if      (z == 0) { A = xr; W = Wr; C = r; }
    else if (z == 1) { A = xk; W = Wk; C = k; }
    else if (z == 2) { A = xv; W = Wv; C = v; }
    else             { A = xg; W = Wg; C = g; epi = 2; }
    tf32_body(A, W, C, nullptr, BT, Cc, Cc, Cc, epi);
}

// ---------------------------------------------------------------------------
// Fused 5-way mix GEMM (unchanged)
// ---------------------------------------------------------------------------
__global__ __launch_bounds__(256)
void mix5_kernel(const float* __restrict__ hsrc, const float* __restrict__ W2,
                 const float* __restrict__ m0p, const float* __restrict__ m1p,
                 const float* __restrict__ m2p, const float* __restrict__ m3p,
                 const float* __restrict__ m4p,
                 const float* __restrict__ x, const float* __restrict__ xx,
                 float* __restrict__ o0, float* __restrict__ o1,
                 float* __restrict__ o2, float* __restrict__ o3,
                 float* __restrict__ o4)
{
    __shared__ float As[32][68];
    __shared__ float Bs[32][68];

    int tid = threadIdx.x;
    int tx = tid & 15, ty = tid >> 4;
    int m0 = blockIdx.y * 64;
    int n0 = blockIdx.x * 64;

    float acc[5][4][4];
#pragma unroll
    for (int f = 0; f < 5; f++)
#pragma unroll
        for (int i = 0; i < 4; i++)
#pragma unroll
            for (int j = 0; j < 4; j++) acc[f][i][j] = 0.f;

    int arow = tid >> 2;
    int aq   = (tid & 3) * 2;
    int brow = tid >> 3;
    int bq   = (tid & 7) * 8;

    for (int f = 0; f < 5; f++) {
        __syncthreads();
        {
            const float* ap = hsrc + (size_t)(m0 + arow) * 160 + f * 32;
#pragma unroll
            for (int i = 0; i < 2; i++) {
                int col = (aq + i) * 4;
                float4 av = *reinterpret_cast<const float4*>(ap + col);
                As[col + 0][arow] = av.x;
                As[col + 1][arow] = av.y;
                As[col + 2][arow] = av.z;
                As[col + 3][arow] = av.w;
            }
        }
        {
            const float* bp = W2 + (size_t)f * 32 * Cc + (size_t)brow * Cc + n0 + bq;
            *reinterpret_cast<float4*>(&Bs[brow][bq])     = *reinterpret_cast<const float4*>(bp);
            *reinterpret_cast<float4*>(&Bs[brow][bq + 4]) = *reinterpret_cast<const float4*>(bp + 4);
        }
        __syncthreads();

#pragma unroll
        for (int kk = 0; kk < 32; kk++) {
            float4 a4 = *reinterpret_cast<const float4*>(&As[kk][ty * 4]);
            float4 b4 = *reinterpret_cast<const float4*>(&Bs[kk][tx * 4]);
            float ar[4] = {a4.x, a4.y, a4.z, a4.w};
            float br[4] = {b4.x, b4.y, b4.z, b4.w};
#pragma unroll
            for (int i = 0; i < 4; i++)
#pragma unroll
                for (int j = 0; j < 4; j++)
                    acc[f][i][j] = fmaf(ar[i], br[j], acc[f][i][j]);
        }
    }

    int nb = n0 + tx * 4;
    float4 ma[5];
    ma[0] = *reinterpret_cast<const float4*>(m0p + nb);
    ma[1] = *reinterpret_cast<const float4*>(m1p + nb);
    ma[2] = *reinterpret_cast<const float4*>(m2p + nb);
    ma[3] = *reinterpret_cast<const float4*>(m3p + nb);
    ma[4] = *reinterpret_cast<const float4*>(m4p + nb);
    float* outs[5] = {o0, o1, o2, o3, o4};

#pragma unroll
    for (int i = 0; i < 4; i++) {
        size_t base = (size_t)(m0 + ty * 4 + i) * Cc + nb;
        float4 xv  = *reinterpret_cast<const float4*>(x + base);
        float4 xxv = *reinterpret_cast<const float4*>(xx + base);
#pragma unroll
        for (int f = 0; f < 5; f++) {
            float4 o;
            o.x = fmaf(xxv.x, ma[f].x + acc[f][i][0], xv.x);
            o.y = fmaf(xxv.y, ma[f].y + acc[f][i][1], xv.y);
            o.z = fmaf(xxv.z, ma[f].z + acc[f][i][2], xv.z);
            o.w = fmaf(xxv.w, ma[f].w + acc[f][i][3], xv.w);
            *reinterpret_cast<float4*>(outs[f] + base) = o;
        }
    }
}

// ---------------------------------------------------------------------------
// WKV6 recurrence, j-split 2-way. grid = 256 blocks: (b, h, j-half, i-half).
// 128 threads = 4 warps; warp q owns 8 state rows j in [jh*32+q*8, ...+8).
// Each block writes PARTIAL y (sum over its 32 j) to ya (jh=0) / yb (jh=1).
// 4-stage cp.async ring; 2 timesteps per barrier pair.
// Stage layout (floats): [0:32) r, [32:64) k, [64:96) w, [96:128) v-half.
// ---------------------------------------------------------------------------
#define WKV_DEPTH 4
#define STG_F 128

__global__ __launch_bounds__(128)
void wkv_kernel(const float* __restrict__ rg, const float* __restrict__ kg,
                const float* __restrict__ vg, const float* __restrict__ wg,
                const float* __restrict__ u,
                float* __restrict__ ya, float* __restrict__ yb)
{
    int bid  = blockIdx.x;
    int ih   = bid & 1;
    int jh   = (bid >> 1) & 1;
    int h    = (bid >> 2) & 7;
    int b    = bid >> 5;
    int tid  = threadIdx.x;
    int lane = tid & 31;
    int warp = tid >> 5;

    __shared__ __align__(16) float stg[WKV_DEPTH][STG_F];
    __shared__ float part[2][4][32];

    float S[8];
#pragma unroll
    for (int jj = 0; jj < 8; jj++) S[jj] = 0.f;

    float uu[8];
#pragma unroll
    for (int jj = 0; jj < 8; jj++) uu[jj] = u[h * 64 + jh * 32 + warp * 8 + jj];

    const int hbase = h * 64;
    const int jbase = hbase + jh * 32;
    float* ydst = jh ? yb : ya;

    auto refill = [&](int slot, int tt) {
        if (tid < 32) {
            size_t gbase = (size_t)(b * Tc + tt) * Cc;
            const float* src;
            float* dst;
            if (tid < 8)       { src = rg + gbase + jbase + tid * 4;              dst = &stg[slot][tid * 4]; }
            else if (tid < 16) { src = kg + gbase + jbase + (tid - 8) * 4;        dst = &stg[slot][32 + (tid - 8) * 4]; }
            else if (tid < 24) { src = wg + gbase + jbase + (tid - 16) * 4;       dst = &stg[slot][64 + (tid - 16) * 4]; }
            else               { src = vg + gbase + hbase + ih * 32 + (tid - 24) * 4; dst = &stg[slot][96 + (tid - 24) * 4]; }
            uint32_t da = (uint32_t)__cvta_generic_to_shared(dst);
            asm volatile("cp.async.cg.shared.global [%0], [%1], 16;" :: "r"(da), "l"(src));
        }
        asm volatile("cp.async.commit_group;");
    };

    auto step = [&](const float* st, int pslot) {
        float vi = st[96 + lane];
        float y0 = 0.f, y1 = 0.f;
#pragma unroll
        for (int q = 0; q < 2; q++) {
            int j = warp * 8 + q * 4;
            float4 r4 = *reinterpret_cast<const float4*>(st + j);
            float4 k4 = *reinterpret_cast<const float4*>(st + 32 + j);
            float4 w4 = *reinterpret_cast<const float4*>(st + 64 + j);
            float kv, acc;
            kv = k4.x * vi; acc = fmaf(uu[q*4+0], kv, S[q*4+0]); y0 = fmaf(r4.x, acc, y0); S[q*4+0] = fmaf(w4.x, S[q*4+0], kv);
            kv = k4.y * vi; acc = fmaf(uu[q*4+1], kv, S[q*4+1]); y1 = fmaf(r4.y, acc, y1); S[q*4+1] = fmaf(w4.y, S[q*4+1], kv);
            kv = k4.z * vi; acc = fmaf(uu[q*4+2], kv, S[q*4+2]); y0 = fmaf(r4.z, acc, y0); S[q*4+2] = fmaf(w4.z, S[q*4+2], kv);
            kv = k4.w * vi; acc = fmaf(uu[q*4+3], kv, S[q*4+3]); y1 = fmaf(r4.w, acc, y1); S[q*4+3] = fmaf(w4.w, S[q*4+3], kv);
        }
        part[pslot][warp][lane] = y0 + y1;
    };

#pragma unroll
    for (int p = 0; p < WKV_DEPTH; p++) refill(p, p);
    asm volatile("cp.async.wait_group 2;");
    __syncthreads();

    for (int t = 0; t < Tc; t += 2) {
        int s0 = t & 3, s1 = (t + 1) & 3;
        step(&stg[s0][0], 0);
        step(&stg[s1][0], 1);
        __syncthreads();

        if (tid < 32) {
            size_t yo = (size_t)(b * Tc + t) * Cc + hbase + ih * 32 + tid;
            float pa = (part[0][0][tid] + part[0][1][tid]) + (part[0][2][tid] + part[0][3][tid]);
            float pb = (part[1][0][tid] + part[1][1][tid]) + (part[1][2][tid] + part[1][3][tid]);
            ydst[yo]      = pa;
            ydst[yo + Cc] = pb;
        }
        if (t + 4 < Tc) refill(s0, t + 4);
        else            asm volatile("cp.async.commit_group;");
        if (t + 5 < Tc) refill(s1, t + 5);
        else            asm volatile("cp.async.commit_group;");
        asm volatile("cp.async.wait_group 2;");
        __syncthreads();
    }
}

// ---------------------------------------------------------------------------
// GroupNorm + gate; combines the two WKV partial buffers (y = ya + yb).
// ---------------------------------------------------------------------------
__global__ __launch_bounds__(256)
void gn_kernel(const float* __restrict__ ya, const float* __restrict__ yb,
               const float* __restrict__ gsrc,
               const float* __restrict__ lng, const float* __restrict__ lnb,
               float* __restrict__ z)
{
    int warp = threadIdx.x >> 5, lane = threadIdx.x & 31;
    int grp = blockIdx.x * 8 + warp;
    int tg = grp >> 3, h = grp & 7;
    size_t base = (size_t)tg * Cc + h * 64;

    float y0 = ya[base + lane]      + yb[base + lane];
    float y1 = ya[base + 32 + lane] + yb[base + 32 + lane];
    float s  = y0 + y1;
    float ss = y0 * y0 + y1 * y1;
#pragma unroll
    for (int o = 16; o; o >>= 1) {
        s  += __shfl_xor_sync(0xffffffffu, s, o);
        ss += __shfl_xor_sync(0xffffffffu, ss, o);
    }
    float mean = s * (1.f / 64.f);
    float var  = ss * (1.f / 64.f) - mean * mean;
    float rstd = rsqrtf(var + 1e-5f);

    int c0 = h * 64 + lane;
    float z0 = fmaf((y0 - mean) * rstd, lng[c0],      lnb[c0]);
    float z1 = fmaf((y1 - mean) * rstd, lng[c0 + 32], lnb[c0 + 32]);
    z[base + lane]      = z0 * gsrc[base + lane];
    z[base + 32 + lane] = z1 * gsrc[base + 32 + lane];
}

// ---------------------------------------------------------------------------
// Launch
// ---------------------------------------------------------------------------
template <typename T>
static float* devptr(T& sym)
{
    void* p = nullptr;
    cudaGetSymbolAddress(&p, sym);
    return (float*)p;
}

extern "C" void kernel_launch(void* const* d_in, const int* in_sizes, int n_in,
                              void* d_out, int out_size)
{
    const float* x      = (const float*)d_in[0];
    const float* maa_x  = (const float*)d_in[1];
    const float* maa_w  = (const float*)d_in[2];
    const float* maa_k  = (const float*)d_in[3];
    const float* maa_v  = (const float*)d_in[4];
    const float* maa_r  = (const float*)d_in[5];
    const float* maa_g  = (const float*)d_in[6];
    const float* W1     = (const float*)d_in[7];   // [512,160]
    const float* W2     = (const float*)d_in[8];   // [5,32,512]
    const float* tdec   = (const float*)d_in[9];   // [512]
    const float* dw1    = (const float*)d_in[10];  // [512,64]
    const float* dw2    = (const float*)d_in[11];  // [64,512]
    const float* faaaa  = (const float*)d_in[12];  // [8,64]
    const float* Wr     = (const float*)d_in[13];
    const float* Wk     = (const float*)d_in[14];
    const float* Wv     = (const float*)d_in[15];
    const float* Wg     = (const float*)d_in[16];
    const float* Wo     = (const float*)d_in[17];
    const float* ln_g   = (const float*)d_in[18];
    const float* ln_b   = (const float*)d_in[19];
    float* out = (float*)d_out;

    float* p_xx   = devptr(g_xx);
    float* p_xxx  = devptr(g_xxx);
    float* p_h    = devptr(g_h);
    float* p_xw   = devptr(g_xw);
    float* p_xk   = devptr(g_xk);
    float* p_xv   = devptr(g_xv);
    float* p_xr   = devptr(g_xr);
    float* p_xg   = devptr(g_xg);
    float* p_r    = devptr(g_r);
    float* p_k    = devptr(g_k);
    float* p_v    = devptr(g_v);
    float* p_gate = devptr(g_gate);
    float* p_wp   = devptr(g_wp);
    float* p_w    = devptr(g_w);
    float* p_y    = devptr(g_y);
    float* p_y2   = devptr(g_y2);
    float* p_z    = devptr(g_z);
    float* p_w1t  = devptr(g_w1t);
    float* p_dw1t = devptr(g_dw1t);
    float* p_dw2t = devptr(g_dw2t);

    const int ewGrid = (BTC + 255) / 256;

    // 0) weight transposes (tiny)
    transpose_pad<<<(256*512 + 128*512 + 512*64) / 256, 256>>>(
        W1, dw1, dw2, p_w1t, p_dw1t, p_dw2t);

    // 1) token shift + xxx
    ew_shift_mix<<<ewGrid, 256>>>(x, maa_x, p_xx, p_xxx);

    // 2) h = tanh(xxx @ W1)   (tf32, N padded to 256)
    {
        dim3 grid(2, BT / 128);
        tf32_gemm<<<grid, 256>>>(p_xxx, p_w1t, p_h, nullptr, BT, Cc, 160, 160, 1);
    }
    // 3) fused mix: x_f = x + xx*(maa_f + h[:,f] @ W2[f])
    {
        dim3 grid(Cc / 64, BT / 64);
        mix5_kernel<<<grid, 256>>>(p_h, W2, maa_w, maa_k, maa_v, maa_r, maa_g,
                                   x, p_xx, p_xw, p_xk, p_xv, p_xr, p_xg);
    }

    // 4) projections r, k, v, g  (tf32, batched single launch)
    {
        dim3 grid(Cc / 128, BT / 128, 4);
        proj4_kernel<<<grid, 256>>>(p_xr, p_xk, p_xv, p_xg,
                                    Wr, Wk, Wv, Wg,
                                    p_r, p_k, p_v, p_gate);
    }
    // 5) decay path (tf32): wp = tanh(xw @ dw1);  w = exp(-exp(tdec + wp @ dw2))
    {
        dim3 grid1(1, BT / 128);
        tf32_gemm<<<grid1, 256>>>(p_xw, p_dw1t, p_wp, nullptr, BT, Cc, 64, 64, 1);
        dim3 grid2(4, BT / 128);
        tf32_gemm<<<grid2, 256>>>(p_wp, p_dw2t, p_w, tdec, BT, 64, Cc, Cc, 3);
    }

    // 6) WKV6 recurrence (j-split 2-way, partials into y / y2)
    wkv_kernel<<<Bc * Hc * 4, 128>>>(p_r, p_k, p_v, p_w, faaaa, p_y, p_y2);

    // 7) GroupNorm + gate (combines partials)
    gn_kernel<<<(BT * Hc) / 8, 256>>>(p_y, p_y2, p_gate, ln_g, ln_b, p_z);

    // 8) out = z @ Wo^T  (tf32)
    {
        dim3 grid(4, BT / 128);
        tf32_gemm<<<grid, 256>>>(p_z, Wo, out, nullptr, BT, Cc, Cc, Cc, 0);
    }
}

// round 11
// speedup vs baseline: 1.1911x; 1.1911x over previous
#include <cuda_runtime.h>
#include <cuda_fp16.h>
#include <math.h>
#include <stdint.h>

// Problem constants
#define Bc   8
#define Tc   2048
#define Cc   512
#define Hc   8
#define Nc   64
#define DMIX 32
#define DDEC 64
#define BT   (Bc*Tc)           // 16384
#define BTC  (BT*Cc)           // 8388608

// ---------------------------------------------------------------------------
// Scratch (static device globals; no allocation allowed)
// ---------------------------------------------------------------------------
__device__ float  g_xx  [BTC];
__device__ float  g_xxx [BTC];
__device__ float  g_h   [BT*160];
__device__ float  g_xw  [BTC];
__device__ float  g_r   [BTC];
__device__ float  g_k   [BTC];
__device__ float  g_v   [BTC];
__device__ float  g_gate[BTC];
__device__ float  g_wp  [BT*DDEC];
__device__ float  g_w   [BTC];
__device__ float  g_y   [BTC];    // WKV partial (j-half 0)
__device__ float  g_y2  [BTC];    // WKV partial (j-half 1)
__device__ float  g_w1t [256*512];
__device__ float  g_dw1t[128*512];
__device__ float  g_dw2t[512*64];
// fp16 operands for the big GEMMs
__device__ __half g_hxr [BTC];
__device__ __half g_hxk [BTC];
__device__ __half g_hxv [BTC];
__device__ __half g_hxg [BTC];
__device__ __half g_hz  [BTC];
__device__ __half g_hWr [Cc*Cc];
__device__ __half g_hWk [Cc*Cc];
__device__ __half g_hWv [Cc*Cc];
__device__ __half g_hWg [Cc*Cc];
__device__ __half g_hWo [Cc*Cc];

// ---------------------------------------------------------------------------
// Elementwise: token shift + xxx = x + xx * maa_x
// ---------------------------------------------------------------------------
__global__ void ew_shift_mix(const float* __restrict__ x,
                             const float* __restrict__ maa_x,
                             float* __restrict__ xx, float* __restrict__ xxx)
{
    int idx = blockIdx.x * 256 + threadIdx.x;
    if (idx >= BTC) return;
    int c  = idx & (Cc - 1);
    int tg = idx >> 9;
    int tt = tg & (Tc - 1);
    float xi = x[idx];
    float xs = (tt > 0) ? x[idx - Cc] : 0.f;
    float xxv = xs - xi;
    xx[idx]  = xxv;
    xxx[idx] = fmaf(xxv, maa_x[c], xi);
}

// ---------------------------------------------------------------------------
// Weight transpose + zero-pad + fp16 weight conversion (tiny, once per call)
// ---------------------------------------------------------------------------
__global__ void transpose_pad(const float* __restrict__ W1,
                              const float* __restrict__ dw1,
                              const float* __restrict__ dw2,
                              float* __restrict__ w1t,
                              float* __restrict__ dw1t,
                              float* __restrict__ dw2t)
{
    int idx = blockIdx.x * 256 + threadIdx.x;
    if (idx < 256 * 512) {
        int n = idx >> 9, k = idx & 511;
        w1t[idx] = (n < 160) ? W1[k * 160 + n] : 0.f;
    } else if (idx < 256 * 512 + 128 * 512) {
        int j = idx - 256 * 512;
        int n = j >> 9, k = j & 511;
        dw1t[j] = (n < 64) ? dw1[k * 64 + n] : 0.f;
    } else if (idx < 256 * 512 + 128 * 512 + 512 * 64) {
        int j = idx - (256 * 512 + 128 * 512);
        int n = j >> 6, k = j & 63;
        dw2t[j] = dw2[k * 512 + n];
    }
}

__global__ void conv_weights_h(const float* __restrict__ Wr, const float* __restrict__ Wk,
                               const float* __restrict__ Wv, const float* __restrict__ Wg,
                               const float* __restrict__ Wo,
                               __half* __restrict__ hWr, __half* __restrict__ hWk,
                               __half* __restrict__ hWv, __half* __restrict__ hWg,
                               __half* __restrict__ hWo)
{
    int idx = blockIdx.x * 256 + threadIdx.x;
    if (idx >= Cc * Cc) return;
    hWr[idx] = __float2half(Wr[idx]);
    hWk[idx] = __float2half(Wk[idx]);
    hWv[idx] = __float2half(Wv[idx]);
    hWg[idx] = __float2half(Wg[idx]);
    hWo[idx] = __float2half(Wo[idx]);
}

// ---------------------------------------------------------------------------
// FP16 tensor-core GEMM (m16n8k16, fp32 accum):
//   C[M,512] = epi( A[M,512] @ W[512,512]^T ), A/W fp16, C fp32.
//   128x128 tile, BK=32, 2-stage cp.async. epi: 0 none, 2 silu.
// ---------------------------------------------------------------------------
__device__ __forceinline__ void h16_body(const __half* __restrict__ A,
                                         const __half* __restrict__ W,
                                         float* __restrict__ Cm, int epi)
{
    __shared__ __half As[2][128][40];
    __shared__ __half Bs[2][128][40];

    int tid  = threadIdx.x;
    int warp = tid >> 5, lane = tid & 31;
    int wm = (warp >> 2) * 64;
    int wn = (warp & 3) * 32;
    int gid = lane >> 2, tig = lane & 3;
    int m0 = blockIdx.y * 128, n0 = blockIdx.x * 128;

    float acc[4][4][4];
#pragma unroll
    for (int mt = 0; mt < 4; mt++)
#pragma unroll
        for (int nt = 0; nt < 4; nt++)
#pragma unroll
            for (int d = 0; d < 4; d++) acc[mt][nt][d] = 0.f;

    auto stage = [&](int buf, int k0) {
#pragma unroll
        for (int it = 0; it < 2; it++) {
            int c = tid + it * 256;       // 0..511
            int row = c >> 2, j = c & 3;  // 4x 16B chunks per 64B row
            uint32_t da = (uint32_t)__cvta_generic_to_shared(&As[buf][row][j * 8]);
            asm volatile("cp.async.cg.shared.global [%0], [%1], 16;"
                         :: "r"(da), "l"(A + (size_t)(m0 + row) * 512 + k0 + j * 8));
            uint32_t db = (uint32_t)__cvta_generic_to_shared(&Bs[buf][row][j * 8]);
            asm volatile("cp.async.cg.shared.global [%0], [%1], 16;"
                         :: "r"(db), "l"(W + (size_t)(n0 + row) * 512 + k0 + j * 8));
        }
        asm volatile("cp.async.commit_group;");
    };

    stage(0, 0);
    stage(1, 32);
    asm volatile("cp.async.wait_group 1;");
    __syncthreads();

    for (int i = 0; i < 16; i++) {
        int buf = i & 1;

#pragma unroll
        for (int ks = 0; ks < 2; ks++) {
            int kb = ks * 16;
            uint32_t afr[4][4];
#pragma unroll
            for (int mt = 0; mt < 4; mt++) {
                int m = wm + mt * 16;
                afr[mt][0] = *reinterpret_cast<const uint32_t*>(&As[buf][m + gid    ][kb + tig * 2    ]);
                afr[mt][1] = *reinterpret_cast<const uint32_t*>(&As[buf][m + gid + 8][kb + tig * 2    ]);
                afr[mt][2] = *reinterpret_cast<const uint32_t*>(&As[buf][m + gid    ][kb + tig * 2 + 8]);
                afr[mt][3] = *reinterpret_cast<const uint32_t*>(&As[buf][m + gid + 8][kb + tig * 2 + 8]);
            }
            uint32_t bfr[4][2];
#pragma unroll
            for (int nt = 0; nt < 4; nt++) {
                int n = wn + nt * 8;
                bfr[nt][0] = *reinterpret_cast<const uint32_t*>(&Bs[buf][n + gid][kb + tig * 2    ]);
                bfr[nt][1] = *reinterpret_cast<const uint32_t*>(&Bs[buf][n + gid][kb + tig * 2 + 8]);
            }
#pragma unroll
            for (int mt = 0; mt < 4; mt++)
#pragma unroll
                for (int nt = 0; nt < 4; nt++) {
                    asm volatile(
                        "mma.sync.aligned.m16n8k16.row.col.f32.f16.f16.f32 "
                        "{%0,%1,%2,%3}, {%4,%5,%6,%7}, {%8,%9}, {%0,%1,%2,%3};"
                        : "+f"(acc[mt][nt][0]), "+f"(acc[mt][nt][1]),
                          "+f"(acc[mt][nt][2]), "+f"(acc[mt][nt][3])
                        : "r"(afr[mt][0]), "r"(afr[mt][1]),
                          "r"(afr[mt][2]), "r"(afr[mt][3]),
                          "r"(bfr[nt][0]), "r"(bfr[nt][1]));
                }
        }

        __syncthreads();
        if (i + 2 < 16) stage(buf, (i + 2) * 32);
        else            asm volatile("cp.async.commit_group;");
        asm volatile("cp.async.wait_group 1;");
        __syncthreads();
    }

#pragma unroll
    for (int mt = 0; mt < 4; mt++) {
        int m = m0 + wm + mt * 16 + gid;
#pragma unroll
        for (int nt = 0; nt < 4; nt++) {
            int n = n0 + wn + nt * 8 + 2 * tig;
            float v0 = acc[mt][nt][0], v1 = acc[mt][nt][1];
            float v2 = acc[mt][nt][2], v3 = acc[mt][nt][3];
            if (epi == 2) {
                v0 = v0 / (1.f + expf(-v0));
                v1 = v1 / (1.f + expf(-v1));
                v2 = v2 / (1.f + expf(-v2));
                v3 = v3 / (1.f + expf(-v3));
            }
            *reinterpret_cast<float2*>(&Cm[(size_t)m * 512 + n])       = make_float2(v0, v1);
            *reinterpret_cast<float2*>(&Cm[(size_t)(m + 8) * 512 + n]) = make_float2(v2, v3);
        }
    }
}

// 4 projections in one launch (blockIdx.z selects), fp16
__global__ __launch_bounds__(256)
void proj4_h(const __half* __restrict__ xr, const __half* __restrict__ xk,
             const __half* __restrict__ xv, const __half* __restrict__ xg,
             const __half* __restrict__ hWr, const __half* __restrict__ hWk,
             const __half* __restrict__ hWv, const __half* __restrict__ hWg,
             float* __restrict__ r, float* __restrict__ k,
             float* __restrict__ v, float* __restrict__ g)
{
    const __half* A; const __half* W; float* C; int epi = 0;
    int z = blockIdx.z;
    if      (z == 0) { A = xr; W = hWr; C = r; }
    else if (z == 1) { A = xk; W = hWk; C = k; }
    else if (z == 2) { A = xv; W = hWv; C = v; }
    else             { A = xg; W = hWg; C = g; epi = 2; }
    h16_body(A, W, C, epi);
}

__global__ __launch_bounds__(256)
void out_h(const __half* __restrict__ z, const __half* __restrict__ hWo,
           float* __restrict__ out)
{
    h16_body(z, hWo, out, 0);
}

// ---------------------------------------------------------------------------
// TF32 tensor-core GEMM (kept for small GEMMs: h, wp, w)
// ---------------------------------------------------------------------------
__device__ __forceinline__ uint32_t f2tf32(float x)
{
    uint32_t u;
    asm("cvt.rna.tf32.f32 %0, %1;" : "=r"(u) : "f"(x));
    return u;
}

__device__ __forceinline__ void tf32_body(const float* __restrict__ A,
                                          const float* __restrict__ W,
                                          float* __restrict__ Cm,
                                          const float* __restrict__ bias,
                                          int M, int K, int Nreal, int ldc, int epi)
{
    __shared__ float As[2][128][20];
    __shared__ float Bs[2][128][20];

    int tid  = threadIdx.x;
    int warp = tid >> 5, lane = tid & 31;
    int wm = (warp >> 2) * 64;
    int wn = (warp & 3) * 32;
    int gid = lane >> 2, tig = lane & 3;
    int m0 = blockIdx.y * 128, n0 = blockIdx.x * 128;

    int lr = tid >> 1;
    int lq = (tid & 1) * 2;
    const float* Aptr = A + (size_t)(m0 + lr) * K;
    const float* Wptr = W + (size_t)(n0 + lr) * K;

    float acc[4][4][4];
#pragma unroll
    for (int mt = 0; mt < 4; mt++)
#pragma unroll
        for (int nt = 0; nt < 4; nt++)
#pragma unroll
            for (int d = 0; d < 4; d++) acc[mt][nt][d] = 0.f;

    auto stage = [&](int buf, int k0) {
#pragma unroll
        for (int i = 0; i < 2; i++) {
            int kq = (lq + i) * 4;
            uint32_t da = (uint32_t)__cvta_generic_to_shared(&As[buf][lr][kq]);
            asm volatile("cp.async.cg.shared.global [%0], [%1], 16;"
                         :: "r"(da), "l"(Aptr + k0 + kq));
            uint32_t db = (uint32_t)__cvta_generic_to_shared(&Bs[buf][lr][kq]);
            asm volatile("cp.async.cg.shared.global [%0], [%1], 16;"
                         :: "r"(db), "l"(Wptr + k0 + kq));
        }
        asm volatile("cp.async.commit_group;");
    };

    int ntiles = K >> 4;
    stage(0, 0);
    if (ntiles > 1) stage(1, 16); else asm volatile("cp.async.commit_group;");
    asm volatile("cp.async.wait_group 1;");
    __syncthreads();

    for (int i = 0; i < ntiles; i++) {
        int buf = i & 1;

#pragma unroll
        for (int ks = 0; ks < 2; ks++) {
            int kb = ks * 8;
            uint32_t afr[4][4];
#pragma unroll
            for (int mt = 0; mt < 4; mt++) {
                int m = wm + mt * 16;
                afr[mt][0] = f2tf32(As[buf][m + gid    ][kb + tig    ]);
                afr[mt][1] = f2tf32(As[buf][m + gid + 8][kb + tig    ]);
                afr[mt][2] = f2tf32(As[buf][m + gid    ][kb + tig + 4]);
                afr[mt][3] = f2tf32(As[buf][m + gid + 8][kb + tig + 4]);
            }
            uint32_t bfr[4][2];
#pragma unroll
            for (int nt = 0; nt < 4; nt++) {
                int n = wn + nt * 8;
                bfr[nt][0] = f2tf32(Bs[buf][n + gid][kb + tig    ]);
                bfr[nt][1] = f2tf32(Bs[buf][n + gid][kb + tig + 4]);
            }
#pragma unroll
            for (int mt = 0; mt < 4; mt++)
#pragma unroll
                for (int nt = 0; nt < 4; nt++) {
                    asm volatile(
                        "mma.sync.aligned.m16n8k8.row.col.f32.tf32.tf32.f32 "
                        "{%0,%1,%2,%3}, {%4,%5,%6,%7}, {%8,%9}, {%0,%1,%2,%3};"
                        : "+f"(acc[mt][nt][0]), "+f"(acc[mt][nt][1]),
                          "+f"(acc[mt][nt][2]), "+f"(acc[mt][nt][3])
                        : "r"(afr[mt][0]), "r"(afr[mt][1]),
                          "r"(afr[mt][2]), "r"(afr[mt][3]),
                          "r"(bfr[nt][0]), "r"(bfr[nt][1]));
                }
        }

        __syncthreads();
        if (i + 2 < ntiles) stage(buf, (i + 2) * 16);
        else                asm volatile("cp.async.commit_group;");
        asm volatile("cp.async.wait_group 1;");
        __syncthreads();
    }

#pragma unroll
    for (int mt = 0; mt < 4; mt++) {
        int m = m0 + wm + mt * 16 + gid;
#pragma unroll
        for (int nt = 0; nt < 4; nt++) {
            int gb = n0 + wn + nt * 8;
            if (gb >= Nreal) continue;
            int n = gb + 2 * tig;
            float v0 = acc[mt][nt][0], v1 = acc[mt][nt][1];
            float v2 = acc[mt][nt][2], v3 = acc[mt][nt][3];
            if (epi == 1) {
                v0 = tanhf(v0); v1 = tanhf(v1); v2 = tanhf(v2); v3 = tanhf(v3);
            } else if (epi == 3) {
                float b0 = bias[n], b1 = bias[n + 1];
                v0 = expf(-expf(b0 + v0));
                v1 = expf(-expf(b1 + v1));
                v2 = expf(-expf(b0 + v2));
                v3 = expf(-expf(b1 + v3));
            }
            *reinterpret_cast<float2*>(&Cm[(size_t)m * ldc + n])       = make_float2(v0, v1);
            *reinterpret_cast<float2*>(&Cm[(size_t)(m + 8) * ldc + n]) = make_float2(v2, v3);
        }
    }
}

__global__ __launch_bounds__(256)
void tf32_gemm(const float* __restrict__ A, const float* __restrict__ W,
               float* __restrict__ C, const float* __restrict__ bias,
               int M, int K, int Nreal, int ldc, int epi)
{
    tf32_body(A, W, C, bias, M, K, Nreal, ldc, epi);
}

// ---------------------------------------------------------------------------
// Fused 5-way mix GEMM. Writes xw fp32; xk/xv/xr/xg as fp16 (GEMM operands).
// ---------------------------------------------------------------------------
__global__ __launch_bounds__(256)
void mix5_kernel(const float* __restrict__ hsrc, const float* __restrict__ W2,
                 const float* __restrict__ m0p, const float* __restrict__ m1p,
                 const float* __restrict__ m2p, const float* __restrict__ m3p,
                 const float* __restrict__ m4p,
                 const float* __restrict__ x, const float* __restrict__ xx,
                 float* __restrict__ o_xw,
                 __half* __restrict__ o_xk, __half* __restrict__ o_xv,
                 __half* __restrict__ o_xr, __half* __restrict__ o_xg)
{
    __shared__ float As[32][68];
    __shared__ float Bs[32][68];

    int tid = threadIdx.x;
    int tx = tid & 15, ty = tid >> 4;
    int m0 = blockIdx.y * 64;
    int n0 = blockIdx.x * 64;

    float acc[5][4][4];
#pragma unroll
    for (int f = 0; f < 5; f++)
#pragma unroll
        for (int i = 0; i < 4; i++)
#pragma unroll
            for (int j = 0; j < 4; j++) acc[f][i][j] = 0.f;

    int arow = tid >> 2;
    int aq   = (tid & 3) * 2;
    int brow = tid >> 3;
    int bq   = (tid & 7) * 8;

    for (int f = 0; f < 5; f++) {
        __syncthreads();
        {
            const float* ap = hsrc + (size_t)(m0 + arow) * 160 + f * 32;
#pragma unroll
            for (int i = 0; i < 2; i++) {
                int col = (aq + i) * 4;
                float4 av = *reinterpret_cast<const float4*>(ap + col);
                As[col + 0][arow] = av.x;
                As[col + 1][arow] = av.y;
                As[col + 2][arow] = av.z;
                As[col + 3][arow] = av.w;
            }
        }
        {
            const float* bp = W2 + (size_t)f * 32 * Cc + (size_t)brow * Cc + n0 + bq;
            *reinterpret_cast<float4*>(&Bs[brow][bq])     = *reinterpret_cast<const float4*>(bp);
            *reinterpret_cast<float4*>(&Bs[brow][bq + 4]) = *reinterpret_cast<const float4*>(bp + 4);
        }
        __syncthreads();

#pragma unroll
        for (int kk = 0; kk < 32; kk++) {
            float4 a4 = *reinterpret_cast<const float4*>(&As[kk][ty * 4]);
            float4 b4 = *reinterpret_cast<const float4*>(&Bs[kk][tx * 4]);
            float ar[4] = {a4.x, a4.y, a4.z, a4.w};
            float br[4] = {b4.x, b4.y, b4.z, b4.w};
#pragma unroll
            for (int i = 0; i < 4; i++)
#pragma unroll
                for (int j = 0; j < 4; j++)
                    acc[f][i][j] = fmaf(ar[i], br[j], acc[f][i][j]);
        }
    }

    int nb = n0 + tx * 4;
    float4 ma[5];
    ma[0] = *reinterpret_cast<const float4*>(m0p + nb);
    ma[1] = *reinterpret_cast<const float4*>(m1p + nb);
    ma[2] = *reinterpret_cast<const float4*>(m2p + nb);
    ma[3] = *reinterpret_cast<const float4*>(m3p + nb);
    ma[4] = *reinterpret_cast<const float4*>(m4p + nb);
    __half* houts[5] = {nullptr, o_xk, o_xv, o_xr, o_xg};

#pragma unroll
    for (int i = 0; i < 4; i++) {
        size_t base = (size_t)(m0 + ty * 4 + i) * Cc + nb;
        float4 xv  = *reinterpret_cast<const float4*>(x + base);
        float4 xxv = *reinterpret_cast<const float4*>(xx + base);
#pragma unroll
        for (int f = 0; f < 5; f++) {
            float4 o;
            o.x = fmaf(xxv.x, ma[f].x + acc[f][i][0], xv.x);
            o.y = fmaf(xxv.y, ma[f].y + acc[f][i][1], xv.y);
            o.z = fmaf(xxv.z, ma[f].z + acc[f][i][2], xv.z);
            o.w = fmaf(xxv.w, ma[f].w + acc[f][i][3], xv.w);
            if (f == 0) {
                *reinterpret_cast<float4*>(o_xw + base) = o;
            } else {
                __half2* hp = reinterpret_cast<__half2*>(houts[f] + base);
                hp[0] = __floats2half2_rn(o.x, o.y);
                hp[1] = __floats2half2_rn(o.z, o.w);
            }
        }
    }
}

// ---------------------------------------------------------------------------
// WKV6 recurrence, j-split 2-way (unchanged from round 10 passing version).
// ---------------------------------------------------------------------------
#define WKV_DEPTH 4
#define STG_F 128

__global__ __launch_bounds__(128)
void wkv_kernel(const float* __restrict__ rg, const float* __restrict__ kg,
                const float* __restrict__ vg, const float* __restrict__ wg,
                const float* __restrict__ u,
                float* __restrict__ ya, float* __restrict__ yb)
{
    int bid  = blockIdx.x;
    int ih   = bid & 1;
    int jh   = (bid >> 1) & 1;
    int h    = (bid >> 2) & 7;
    int b    = bid >> 5;
    int tid  = threadIdx.x;
    int lane = tid & 31;
    int warp = tid >> 5;

    __shared__ __align__(16) float stg[WKV_DEPTH][STG_F];
    __shared__ float part[2][4][32];

    float S[8];
#pragma unroll
    for (int jj = 0; jj < 8; jj++) S[jj] = 0.f;

    float uu[8];
#pragma unroll
    for (int jj = 0; jj < 8; jj++) uu[jj] = u[h * 64 + jh * 32 + warp * 8 + jj];

    const int hbase = h * 64;
    const int jbase = hbase + jh * 32;
    float* ydst = jh ? yb : ya;

    auto refill = [&](int slot, int tt) {
        if (tid < 32) {
            size_t gbase = (size_t)(b * Tc + tt) * Cc;
            const float* src;
            float* dst;
            if (tid < 8)       { src = rg + gbase + jbase + tid * 4;              dst = &stg[slot][tid * 4]; }
            else if (tid < 16) { src = kg + gbase + jbase + (tid - 8) * 4;        dst = &stg[slot][32 + (tid - 8) * 4]; }
            else if (tid < 24) { src = wg + gbase + jbase + (tid - 16) * 4;       dst = &stg[slot][64 + (tid - 16) * 4]; }
            else               { src = vg + gbase + hbase + ih * 32 + (tid - 24) * 4; dst = &stg[slot][96 + (tid - 24) * 4]; }
            uint32_t da = (uint32_t)__cvta_generic_to_shared(dst);
            asm volatile("cp.async.cg.shared.global [%0], [%1], 16;" :: "r"(da), "l"(src));
        }
        asm volatile("cp.async.commit_group;");
    };

    auto step = [&](const float* st, int pslot) {
        float vi = st[96 + lane];
        float y0 = 0.f, y1 = 0.f;
#pragma unroll
        for (int q = 0; q < 2; q++) {
            int j = warp * 8 + q * 4;
            float4 r4 = *reinterpret_cast<const float4*>(st + j);
            float4 k4 = *reinterpret_cast<const float4*>(st + 32 + j);
            float4 w4 = *reinterpret_cast<const float4*>(st + 64 + j);
            float kv, acc;
            kv = k4.x * vi; acc = fmaf(uu[q*4+0], kv, S[q*4+0]); y0 = fmaf(r4.x, acc, y0); S[q*4+0] = fmaf(w4.x, S[q*4+0], kv);
            kv = k4.y * vi; acc = fmaf(uu[q*4+1], kv, S[q*4+1]); y1 = fmaf(r4.y, acc, y1); S[q*4+1] = fmaf(w4.y, S[q*4+1], kv);
            kv = k4.z * vi; acc = fmaf(uu[q*4+2], kv, S[q*4+2]); y0 = fmaf(r4.z, acc, y0); S[q*4+2] = fmaf(w4.z, S[q*4+2], kv);
            kv = k4.w * vi; acc = fmaf(uu[q*4+3], kv, S[q*4+3]); y1 = fmaf(r4.w, acc, y1); S[q*4+3] = fmaf(w4.w, S[q*4+3], kv);
        }
        part[pslot][warp][lane] = y0 + y1;
    };

#pragma unroll
    for (int p = 0; p < WKV_DEPTH; p++) refill(p, p);
    asm volatile("cp.async.wait_group 2;");
    __syncthreads();

    for (int t = 0; t < Tc; t += 2) {
        int s0 = t & 3, s1 = (t + 1) & 3;
        step(&stg[s0][0], 0);
        step(&stg[s1][0], 1);
        __syncthreads();

        if (tid < 32) {
            size_t yo = (size_t)(b * Tc + t) * Cc + hbase + ih * 32 + tid;
            float pa = (part[0][0][tid] + part[0][1][tid]) + (part[0][2][tid] + part[0][3][tid]);
            float pb = (part[1][0][tid] + part[1][1][tid]) + (part[1][2][tid] + part[1][3][tid]);
            ydst[yo]      = pa;
            ydst[yo + Cc] = pb;
        }
        if (t + 4 < Tc) refill(s0, t + 4);
        else            asm volatile("cp.async.commit_group;");
        if (t + 5 < Tc) refill(s1, t + 5);
        else            asm volatile("cp.async.commit_group;");
        asm volatile("cp.async.wait_group 2;");
        __syncthreads();
    }
}

// ---------------------------------------------------------------------------
// GroupNorm + gate; combines WKV partials; writes fp16 z for the out GEMM.
// ---------------------------------------------------------------------------
__global__ __launch_bounds__(256)
void gn_kernel(const float* __restrict__ ya, const float* __restrict__ yb,
               const float* __restrict__ gsrc,
               const float* __restrict__ lng, const float* __restrict__ lnb,
               __half* __restrict__ hz)
{
    int warp = threadIdx.x >> 5, lane = threadIdx.x & 31;
    int grp = blockIdx.x * 8 + warp;
    int tg = grp >> 3, h = grp & 7;
    size_t base = (size_t)tg * Cc + h * 64;

    float y0 = ya[base + lane]      + yb[base + lane];
    float y1 = ya[base + 32 + lane] + yb[base + 32 + lane];
    float s  = y0 + y1;
    float ss = y0 * y0 + y1 * y1;
#pragma unroll
    for (int o = 16; o; o >>= 1) {
        s  += __shfl_xor_sync(0xffffffffu, s, o);
        ss += __shfl_xor_sync(0xffffffffu, ss, o);
    }
    float mean = s * (1.f / 64.f);
    float var  = ss * (1.f / 64.f) - mean * mean;
    float rstd = rsqrtf(var + 1e-5f);

    int c0 = h * 64 + lane;
    float z0 = fmaf((y0 - mean) * rstd, lng[c0],      lnb[c0]) * gsrc[base + lane];
    float z1 = fmaf((y1 - mean) * rstd, lng[c0 + 32], lnb[c0 + 32]) * gsrc[base + 32 + lane];
    hz[base + lane]      = __float2half(z0);
    hz[base + 32 + lane] = __float2half(z1);
}

// ---------------------------------------------------------------------------
// Launch
// ---------------------------------------------------------------------------
template <typename T>
static void* devptr_raw(T& sym)
{
    void* p = nullptr;
    cudaGetSymbolAddress(&p, sym);
    return p;
}

extern "C" void kernel_launch(void* const* d_in, const int* in_sizes, int n_in,
                              void* d_out, int out_size)
{
    const float* x      = (const float*)d_in[0];
    const float* maa_x  = (const float*)d_in[1];
    const float* maa_w  = (const float*)d_in[2];
    const float* maa_k  = (const float*)d_in[3];
    const float* maa_v  = (const float*)d_in[4];
    const float* maa_r  = (const float*)d_in[5];
    const float* maa_g  = (const float*)d_in[6];
    const float* W1     = (const float*)d_in[7];
    const float* W2     = (const float*)d_in[8];
    const float* tdec   = (const float*)d_in[9];
    const float* dw1    = (const float*)d_in[10];
    const float* dw2    = (const float*)d_in[11];
    const float* faaaa  = (const float*)d_in[12];
    const float* Wr     = (const float*)d_in[13];
    const float* Wk     = (const float*)d_in[14];
    const float* Wv     = (const float*)d_in[15];
    const float* Wg     = (const float*)d_in[16];
    const float* Wo     = (const float*)d_in[17];
    const float* ln_g   = (const float*)d_in[18];
    const float* ln_b   = (const float*)d_in[19];
    float* out = (float*)d_out;

    float*  p_xx   = (float*)devptr_raw(g_xx);
    float*  p_xxx  = (float*)devptr_raw(g_xxx);
    float*  p_h    = (float*)devptr_raw(g_h);
    float*  p_xw   = (float*)devptr_raw(g_xw);
    float*  p_r    = (float*)devptr_raw(g_r);
    float*  p_k    = (float*)devptr_raw(g_k);
    float*  p_v    = (float*)devptr_raw(g_v);
    float*  p_gate = (float*)devptr_raw(g_gate);
    float*  p_wp   = (float*)devptr_raw(g_wp);
    float*  p_w    = (float*)devptr_raw(g_w);
    float*  p_y    = (float*)devptr_raw(g_y);
    float*  p_y2   = (float*)devptr_raw(g_y2);
    float*  p_w1t  = (float*)devptr_raw(g_w1t);
    float*  p_dw1t = (float*)devptr_raw(g_dw1t);
    float*  p_dw2t = (float*)devptr_raw(g_dw2t);
    __half* p_hxr  = (__half*)devptr_raw(g_hxr);
    __half* p_hxk  = (__half*)devptr_raw(g_hxk);
    __half* p_hxv  = (__half*)devptr_raw(g_hxv);
    __half* p_hxg  = (__half*)devptr_raw(g_hxg);
    __half* p_hz   = (__half*)devptr_raw(g_hz);
    __half* p_hWr  = (__half*)devptr_raw(g_hWr);
    __half* p_hWk  = (__half*)devptr_raw(g_hWk);
    __half* p_hWv  = (__half*)devptr_raw(g_hWv);
    __half* p_hWg  = (__half*)devptr_raw(g_hWg);
    __half* p_hWo  = (__half*)devptr_raw(g_hWo);

    const int ewGrid = (BTC + 255) / 256;

    // 0) weight prep (tiny)
    transpose_pad<<<(256*512 + 128*512 + 512*64) / 256, 256>>>(
        W1, dw1, dw2, p_w1t, p_dw1t, p_dw2t);
    conv_weights_h<<<(Cc*Cc + 255) / 256, 256>>>(Wr, Wk, Wv, Wg, Wo,
                                                 p_hWr, p_hWk, p_hWv, p_hWg, p_hWo);

    // 1) token shift + xxx
    ew_shift_mix<<<ewGrid, 256>>>(x, maa_x, p_xx, p_xxx);

    // 2) h = tanh(xxx @ W1)   (tf32, N padded to 256)
    {
        dim3 grid(2, BT / 128);
        tf32_gemm<<<grid, 256>>>(p_xxx, p_w1t, p_h, nullptr, BT, Cc, 160, 160, 1);
    }
    // 3) fused mix: xw fp32; xk/xv/xr/xg fp16
    {
        dim3 grid(Cc / 64, BT / 64);
        mix5_kernel<<<grid, 256>>>(p_h, W2, maa_w, maa_k, maa_v, maa_r, maa_g,
                                   x, p_xx, p_xw, p_hxk, p_hxv, p_hxr, p_hxg);
    }

    // 4) projections r, k, v, g  (fp16 m16n8k16, batched single launch)
    {
        dim3 grid(Cc / 128, BT / 128, 4);
        proj4_h<<<grid, 256>>>(p_hxr, p_hxk, p_hxv, p_hxg,
                               p_hWr, p_hWk, p_hWv, p_hWg,
                               p_r, p_k, p_v, p_gate);
    }
    // 5) decay path (tf32): wp = tanh(xw @ dw1);  w = exp(-exp(tdec + wp @ dw2))
    {
        dim3 grid1(1, BT / 128);
        tf32_gemm<<<grid1, 256>>>(p_xw, p_dw1t, p_wp, nullptr, BT, Cc, 64, 64, 1);
        dim3 grid2(4, BT / 128);
        tf32_gemm<<<grid2, 256>>>(p_wp, p_dw2t, p_w, tdec, BT, 64, Cc, Cc, 3);
    }

    // 6) WKV6 recurrence (j-split 2-way)
    wkv_kernel<<<Bc * Hc * 4, 128>>>(p_r, p_k, p_v, p_w, faaaa, p_y, p_y2);

    // 7) GroupNorm + gate -> fp16 z
    gn_kernel<<<(BT * Hc) / 8, 256>>>(p_y, p_y2, p_gate, ln_g, ln_b, p_hz);

    // 8) out = z @ Wo^T  (fp16)
    {
        dim3 grid(Cc / 128, BT / 128);
        out_h<<<grid, 256>>>(p_hz, p_hWo, out);
    }
}

// round 15
// speedup vs baseline: 1.2699x; 1.0662x over previous
#include <cuda_runtime.h>
#include <cuda_fp16.h>
#include <math.h>
#include <stdint.h>

// Problem constants
#define Bc   8
#define Tc   2048
#define Cc   512
#define Hc   8
#define Nc   64
#define DMIX 32
#define DDEC 64
#define BT   (Bc*Tc)           // 16384
#define BTC  (BT*Cc)           // 8388608

// ---------------------------------------------------------------------------
// Scratch (static device globals; no allocation allowed)
// ---------------------------------------------------------------------------
__device__ float  g_xx  [BTC];
__device__ float  g_xxx [BTC];
__device__ __half g_h16 [BT*160];
__device__ float  g_xw  [BTC];
__device__ float  g_r   [BTC];
__device__ float  g_k   [BTC];
__device__ float  g_v   [BTC];
__device__ float  g_gate[BTC];
__device__ float  g_wp  [BT*DDEC];
__device__ float  g_w   [BTC];
__device__ float  g_y   [BTC];    // WKV partial (j-half 0)
__device__ float  g_y2  [BTC];    // WKV partial (j-half 1)
__device__ float  g_w1t [256*512];
__device__ float  g_dw1t[128*512];
__device__ float  g_dw2t[512*64];
// fp16 operands
__device__ __half g_hxr [BTC];
__device__ __half g_hxk [BTC];
__device__ __half g_hxv [BTC];
__device__ __half g_hxg [BTC];
__device__ __half g_hz  [BTC];
__device__ __half g_hWr [Cc*Cc];
__device__ __half g_hWk [Cc*Cc];
__device__ __half g_hWv [Cc*Cc];
__device__ __half g_hWg [Cc*Cc];
__device__ __half g_hWo [Cc*Cc];
__device__ __half g_w2th[5*512*32];   // W2^T fp16: [f][n][k]

// ---------------------------------------------------------------------------
// Elementwise: token shift + xxx = x + xx * maa_x
// ---------------------------------------------------------------------------
__global__ void ew_shift_mix(const float* __restrict__ x,
                             const float* __restrict__ maa_x,
                             float* __restrict__ xx, float* __restrict__ xxx)
{
    int idx = blockIdx.x * 256 + threadIdx.x;
    if (idx >= BTC) return;
    int c  = idx & (Cc - 1);
    int tg = idx >> 9;
    int tt = tg & (Tc - 1);
    float xi = x[idx];
    float xs = (tt > 0) ? x[idx - Cc] : 0.f;
    float xxv = xs - xi;
    xx[idx]  = xxv;
    xxx[idx] = fmaf(xxv, maa_x[c], xi);
}

// ---------------------------------------------------------------------------
// Weight prep (tiny, once per call)
// ---------------------------------------------------------------------------
__global__ void transpose_pad(const float* __restrict__ W1,
                              const float* __restrict__ dw1,
                              const float* __restrict__ dw2,
                              float* __restrict__ w1t,
                              float* __restrict__ dw1t,
                              float* __restrict__ dw2t)
{
    int idx = blockIdx.x * 256 + threadIdx.x;
    if (idx < 256 * 512) {
        int n = idx >> 9, k = idx & 511;
        w1t[idx] = (n < 160) ? W1[k * 160 + n] : 0.f;
    } else if (idx < 256 * 512 + 128 * 512) {
        int j = idx - 256 * 512;
        int n = j >> 9, k = j & 511;
        dw1t[j] = (n < 64) ? dw1[k * 64 + n] : 0.f;
    } else if (idx < 256 * 512 + 128 * 512 + 512 * 64) {
        int j = idx - (256 * 512 + 128 * 512);
        int n = j >> 6, k = j & 63;
        dw2t[j] = dw2[k * 512 + n];
    }
}

__global__ void conv_weights_h(const float* __restrict__ Wr, const float* __restrict__ Wk,
                               const float* __restrict__ Wv, const float* __restrict__ Wg,
                               const float* __restrict__ Wo, const float* __restrict__ W2,
                               __half* __restrict__ hWr, __half* __restrict__ hWk,
                               __half* __restrict__ hWv, __half* __restrict__ hWg,
                               __half* __restrict__ hWo, __half* __restrict__ w2th)
{
    int idx = blockIdx.x * 256 + threadIdx.x;
    if (idx < Cc * Cc) {
        hWr[idx] = __float2half(Wr[idx]);
        hWk[idx] = __float2half(Wk[idx]);
        hWv[idx] = __float2half(Wv[idx]);
        hWg[idx] = __float2half(Wg[idx]);
        hWo[idx] = __float2half(Wo[idx]);
    }
    if (idx < 5 * 512 * 32) {
        int f = idx / (512 * 32);
        int rem = idx - f * 512 * 32;
        int n = rem >> 5, k = rem & 31;
        w2th[idx] = __float2half(W2[(size_t)f * 32 * 512 + (size_t)k * 512 + n]);
    }
}

// ---------------------------------------------------------------------------
// FP16 tensor-core GEMM (m16n8k16, fp32 accum):
//   C[M,512] = epi( A[M,512] @ W[512,512]^T ).  epi: 0 none, 2 silu.
// ---------------------------------------------------------------------------
__device__ __forceinline__ void h16_body(const __half* __restrict__ A,
                                         const __half* __restrict__ W,
                                         float* __restrict__ Cm, int epi)
{
    __shared__ __half As[2][128][40];
    __shared__ __half Bs[2][128][40];

    int tid  = threadIdx.x;
    int warp = tid >> 5, lane = tid & 31;
    int wm = (warp >> 2) * 64;
    int wn = (warp & 3) * 32;
    int gid = lane >> 2, tig = lane & 3;
    int m0 = blockIdx.y * 128, n0 = blockIdx.x * 128;

    float acc[4][4][4];
#pragma unroll
    for (int mt = 0; mt < 4; mt++)
#pragma unroll
        for (int nt = 0; nt < 4; nt++)
#pragma unroll
            for (int d = 0; d < 4; d++) acc[mt][nt][d] = 0.f;

    auto stage = [&](int buf, int k0) {
#pragma unroll
        for (int it = 0; it < 2; it++) {
            int c = tid + it * 256;
            int row = c >> 2, j = c & 3;
            uint32_t da = (uint32_t)__cvta_generic_to_shared(&As[buf][row][j * 8]);
            asm volatile("cp.async.cg.shared.global [%0], [%1], 16;"
                         :: "r"(da), "l"(A + (size_t)(m0 + row) * 512 + k0 + j * 8));
            uint32_t db = (uint32_t)__cvta_generic_to_shared(&Bs[buf][row][j * 8]);
            asm volatile("cp.async.cg.shared.global [%0], [%1], 16;"
                         :: "r"(db), "l"(W + (size_t)(n0 + row) * 512 + k0 + j * 8));
        }
        asm volatile("cp.async.commit_group;");
    };

    stage(0, 0);
    stage(1, 32);
    asm volatile("cp.async.wait_group 1;");
    __syncthreads();

    for (int i = 0; i < 16; i++) {
        int buf = i & 1;

#pragma unroll
        for (int ks = 0; ks < 2; ks++) {
            int kb = ks * 16;
            uint32_t afr[4][4];
#pragma unroll
            for (int mt = 0; mt < 4; mt++) {
                int m = wm + mt * 16;
                afr[mt][0] = *reinterpret_cast<const uint32_t*>(&As[buf][m + gid    ][kb + tig * 2    ]);
                afr[mt][1] = *reinterpret_cast<const uint32_t*>(&As[buf][m + gid + 8][kb + tig * 2    ]);
                afr[mt][2] = *reinterpret_cast<const uint32_t*>(&As[buf][m + gid    ][kb + tig * 2 + 8]);
                afr[mt][3] = *reinterpret_cast<const uint32_t*>(&As[buf][m + gid + 8][kb + tig * 2 + 8]);
            }
            uint32_t bfr[4][2];
#pragma unroll
            for (int nt = 0; nt < 4; nt++) {
                int n = wn + nt * 8;
                bfr[nt][0] = *reinterpret_cast<const uint32_t*>(&Bs[buf][n + gid][kb + tig * 2    ]);
                bfr[nt][1] = *reinterpret_cast<const uint32_t*>(&Bs[buf][n + gid][kb + tig * 2 + 8]);
            }
#pragma unroll
            for (int mt = 0; mt < 4; mt++)
#pragma unroll
                for (int nt = 0; nt < 4; nt++) {
                    asm volatile(
                        "mma.sync.aligned.m16n8k16.row.col.f32.f16.f16.f32 "
                        "{%0,%1,%2,%3}, {%4,%5,%6,%7}, {%8,%9}, {%0,%1,%2,%3};"
                        : "+f"(acc[mt][nt][0]), "+f"(acc[mt][nt][1]),
                          "+f"(acc[mt][nt][2]), "+f"(acc[mt][nt][3])
                        : "r"(afr[mt][0]), "r"(afr[mt][1]),
                          "r"(afr[mt][2]), "r"(afr[mt][3]),
                          "r"(bfr[nt][0]), "r"(bfr[nt][1]));
                }
        }

        __syncthreads();
        if (i + 2 < 16) stage(buf, (i + 2) * 32);
        else            asm volatile("cp.async.commit_group;");
        asm volatile("cp.async.wait_group 1;");
        __syncthreads();
    }

#pragma unroll
    for (int mt = 0; mt < 4; mt++) {
        int m = m0 + wm + mt * 16 + gid;
#pragma unroll
        for (int nt = 0; nt < 4; nt++) {
            int n = n0 + wn + nt * 8 + 2 * tig;
            float v0 = acc[mt][nt][0], v1 = acc[mt][nt][1];
            float v2 = acc[mt][nt][2], v3 = acc[mt][nt][3];
            if (epi == 2) {
                v0 = v0 / (1.f + expf(-v0));
                v1 = v1 / (1.f + expf(-v1));
                v2 = v2 / (1.f + expf(-v2));
                v3 = v3 / (1.f + expf(-v3));
            }
            *reinterpret_cast<float2*>(&Cm[(size_t)m * 512 + n])       = make_float2(v0, v1);
            *reinterpret_cast<float2*>(&Cm[(size_t)(m + 8) * 512 + n]) = make_float2(v2, v3);
        }
    }
}

__global__ __launch_bounds__(256)
void proj4_h(const __half* __restrict__ xr, const __half* __restrict__ xk,
             const __half* __restrict__ xv, const __half* __restrict__ xg,
             const __half* __restrict__ hWr, const __half* __restrict__ hWk,
             const __half* __restrict__ hWv, const __half* __restrict__ hWg,
             float* __restrict__ r, float* __restrict__ k,
             float* __restrict__ v, float* __restrict__ g)
{
    const __half* A; const __half* W; float* C; int epi = 0;
    int z = blockIdx.z;
    if      (z == 0) { A = xr; W = hWr; C = r; }
    else if (z == 1) { A = xk; W = hWk; C = k; }
    else if (z == 2) { A = xv; W = hWv; C = v; }
    else             { A = xg; W = hWg; C = g; epi = 2; }
    h16_body(A, W, C, epi);
}

__global__ __launch_bounds__(256)
void out_h(const __half* __restrict__ z, const __half* __restrict__ hWo,
           float* __restrict__ out)
{
    h16_body(z, hWo, out, 0);
}

// ---------------------------------------------------------------------------
// TF32 GEMM (small GEMMs: h, wp, w). epi: 1 tanh, 3 exp(-exp(bias+v)),
//   4 tanh -> fp16 output (Cm reinterpreted as __half*).
// ---------------------------------------------------------------------------
__device__ __forceinline__ uint32_t f2tf32(float x)
{
    uint32_t u;
    asm("cvt.rna.tf32.f32 %0, %1;" : "=r"(u) : "f"(x));
    return u;
}

__device__ __forceinline__ void tf32_body(const float* __restrict__ A,
                                          const float* __restrict__ W,
                                          float* __restrict__ Cm,
                                          const float* __restrict__ bias,
                                          int M, int K, int Nreal, int ldc, int epi)
{
    __shared__ float As[2][128][20];
    __shared__ float Bs[2][128][20];

    int tid  = threadIdx.x;
    int warp = tid >> 5, lane = tid & 31;
    int wm = (warp >> 2) * 64;
    int wn = (warp & 3) * 32;
    int gid = lane >> 2, tig = lane & 3;
    int m0 = blockIdx.y * 128, n0 = blockIdx.x * 128;

    int lr = tid >> 1;
    int lq = (tid & 1) * 2;
    const float* Aptr = A + (size_t)(m0 + lr) * K;
    const float* Wptr = W + (size_t)(n0 + lr) * K;

    float acc[4][4][4];
#pragma unroll
    for (int mt = 0; mt < 4; mt++)
#pragma unroll
        for (int nt = 0; nt < 4; nt++)
#pragma unroll
            for (int d = 0; d < 4; d++) acc[mt][nt][d] = 0.f;

    auto stage = [&](int buf, int k0) {
#pragma unroll
        for (int i = 0; i < 2; i++) {
            int kq = (lq + i) * 4;
            uint32_t da = (uint32_t)__cvta_generic_to_shared(&As[buf][lr][kq]);
            asm volatile("cp.async.cg.shared.global [%0], [%1], 16;"
                         :: "r"(da), "l"(Aptr + k0 + kq));
            uint32_t db = (uint32_t)__cvta_generic_to_shared(&Bs[buf][lr][kq]);
            asm volatile("cp.async.cg.shared.global [%0], [%1], 16;"
                         :: "r"(db), "l"(Wptr + k0 + kq));
        }
        asm volatile("cp.async.commit_group;");
    };

    int ntiles = K >> 4;
    stage(0, 0);
    if (ntiles > 1) stage(1, 16); else asm volatile("cp.async.commit_group;");
    asm volatile("cp.async.wait_group 1;");
    __syncthreads();

    for (int i = 0; i < ntiles; i++) {
        int buf = i & 1;

#pragma unroll
        for (int ks = 0; ks < 2; ks++) {
            int kb = ks * 8;
            uint32_t afr[4][4];
#pragma unroll
            for (int mt = 0; mt < 4; mt++) {
                int m = wm + mt * 16;
                afr[mt][0] = f2tf32(As[buf][m + gid    ][kb + tig    ]);
                afr[mt][1] = f2tf32(As[buf][m + gid + 8][kb + tig    ]);
                afr[mt][2] = f2tf32(As[buf][m + gid    ][kb + tig + 4]);
                afr[mt][3] = f2tf32(As[buf][m + gid + 8][kb + tig + 4]);
            }
            uint32_t bfr[4][2];
#pragma unroll
            for (int nt = 0; nt < 4; nt++) {
                int n = wn + nt * 8;
                bfr[nt][0] = f2tf32(Bs[buf][n + gid][kb + tig    ]);
                bfr[nt][1] = f2tf32(Bs[buf][n + gid][kb + tig + 4]);
            }
#pragma unroll
            for (int mt = 0; mt < 4; mt++)
#pragma unroll
                for (int nt = 0; nt < 4; nt++) {
                    asm volatile(
                        "mma.sync.aligned.m16n8k8.row.col.f32.tf32.tf32.f32 "
                        "{%0,%1,%2,%3}, {%4,%5,%6,%7}, {%8,%9}, {%0,%1,%2,%3};"
                        : "+f"(acc[mt][nt][0]), "+f"(acc[mt][nt][1]),
                          "+f"(acc[mt][nt][2]), "+f"(acc[mt][nt][3])
                        : "r"(afr[mt][0]), "r"(afr[mt][1]),
                          "r"(afr[mt][2]), "r"(afr[mt][3]),
                          "r"(bfr[nt][0]), "r"(bfr[nt][1]));
                }
        }

        __syncthreads();
        if (i + 2 < ntiles) stage(buf, (i + 2) * 16);
        else                asm volatile("cp.async.commit_group;");
        asm volatile("cp.async.wait_group 1;");
        __syncthreads();
    }

#pragma unroll
    for (int mt = 0; mt < 4; mt++) {
        int m = m0 + wm + mt * 16 + gid;
#pragma unroll
        for (int nt = 0; nt < 4; nt++) {
            int gb = n0 + wn + nt * 8;
            if (gb >= Nreal) continue;
            int n = gb + 2 * tig;
            float v0 = acc[mt][nt][0], v1 = acc[mt][nt][1];
            float v2 = acc[mt][nt][2], v3 = acc[mt][nt][3];
            if (epi == 1 || epi == 4) {
                v0 = tanhf(v0); v1 = tanhf(v1); v2 = tanhf(v2); v3 = tanhf(v3);
            } else if (epi == 3) {
                float b0 = bias[n], b1 = bias[n + 1];
                v0 = expf(-expf(b0 + v0));
                v1 = expf(-expf(b1 + v1));
                v2 = expf(-expf(b0 + v2));
                v3 = expf(-expf(b1 + v3));
            }
            if (epi == 4) {
                __half* hc = reinterpret_cast<__half*>(Cm);
                *reinterpret_cast<__half2*>(&hc[(size_t)m * ldc + n])       = __floats2half2_rn(v0, v1);
                *reinterpret_cast<__half2*>(&hc[(size_t)(m + 8) * ldc + n]) = __floats2half2_rn(v2, v3);
            } else {
                *reinterpret_cast<float2*>(&Cm[(size_t)m * ldc + n])       = make_float2(v0, v1);
                *reinterpret_cast<float2*>(&Cm[(size_t)(m + 8) * ldc + n]) = make_float2(v2, v3);
            }
        }
    }
}

__global__ __launch_bounds__(256)
void tf32_gemm(const float* __restrict__ A, const float* __restrict__ W,
               float* __restrict__ C, const float* __restrict__ bias,
               int M, int K, int Nreal, int ldc, int epi)
{
    tf32_body(A, W, C, bias, M, K, Nreal, ldc, epi);
}

// ---------------------------------------------------------------------------
// mix5h: fp16 tensor-core fused 5-way mix.
//   For f in 0..4: m_f = h16[:, f*32:(f+1)*32] @ W2[f]  (via w2th[f][n][k])
//   out_f = x + xx * (maa_f + m_f);  xw fp32, xk/xv/xr/xg fp16.
//   64x64 tile, 8 warps (4m x 2n). Smem stride 36 halves (72B) -> 46080B.
//   Staging: plain synchronous uint2 (8B) LDG -> STS (no cp.async).
// ---------------------------------------------------------------------------
#define MIX_STR 36

__global__ __launch_bounds__(256)
void mix5h(const __half* __restrict__ h16, const __half* __restrict__ w2th,
           const float* __restrict__ m0p, const float* __restrict__ m1p,
           const float* __restrict__ m2p, const float* __restrict__ m3p,
           const float* __restrict__ m4p,
           const float* __restrict__ x, const float* __restrict__ xx,
           float* __restrict__ o_xw,
           __half* __restrict__ o_xk, __half* __restrict__ o_xv,
           __half* __restrict__ o_xr, __half* __restrict__ o_xg)
{
    __shared__ __half As[5][64][MIX_STR];
    __shared__ __half Bs[5][64][MIX_STR];

    int tid  = threadIdx.x;
    int warp = tid >> 5, lane = tid & 31;
    int wm = (warp >> 1) * 16;        // 0,16,32,48
    int wn = (warp & 1) * 32;         // 0,32
    int gid = lane >> 2, tig = lane & 3;
    int m0 = blockIdx.y * 64, n0 = blockIdx.x * 64;

    // synchronous staging: per f, 64 rows x 32 halves = 512 8-byte chunks
#pragma unroll
    for (int f = 0; f < 5; f++) {
#pragma unroll
        for (int it = 0; it < 2; it++) {
            int c = tid + it * 256;          // 0..511
            int row = c >> 3, j = c & 7;     // 8-byte chunk (4 halves)
            uint2 va = *reinterpret_cast<const uint2*>(
                h16 + (size_t)(m0 + row) * 160 + f * 32 + j * 4);
            *reinterpret_cast<uint2*>(&As[f][row][j * 4]) = va;
            uint2 vb = *reinterpret_cast<const uint2*>(
                w2th + ((size_t)f * 512 + n0 + row) * 32 + j * 4);
            *reinterpret_cast<uint2*>(&Bs[f][row][j * 4]) = vb;
        }
    }
    __syncthreads();

    float acc[5][4][4];
#pragma unroll
    for (int f = 0; f < 5; f++)
#pragma unroll
        for (int nt = 0; nt < 4; nt++)
#pragma unroll
            for (int d = 0; d < 4; d++) acc[f][nt][d] = 0.f;

#pragma unroll
    for (int f = 0; f < 5; f++) {
#pragma unroll
        for (int ks = 0; ks < 2; ks++) {
            int kb = ks * 16;
            uint32_t a0 = *reinterpret_cast<const uint32_t*>(&As[f][wm + gid    ][kb + tig * 2    ]);
            uint32_t a1 = *reinterpret_cast<const uint32_t*>(&As[f][wm + gid + 8][kb + tig * 2    ]);
            uint32_t a2 = *reinterpret_cast<const uint32_t*>(&As[f][wm + gid    ][kb + tig * 2 + 8]);
            uint32_t a3 = *reinterpret_cast<const uint32_t*>(&As[f][wm + gid + 8][kb + tig * 2 + 8]);
#pragma unroll
            for (int nt = 0; nt < 4; nt++) {
                int n = wn + nt * 8;
                uint32_t b0 = *reinterpret_cast<const uint32_t*>(&Bs[f][n + gid][kb + tig * 2    ]);
                uint32_t b1 = *reinterpret_cast<const uint32_t*>(&Bs[f][n + gid][kb + tig * 2 + 8]);
                asm volatile(
                    "mma.sync.aligned.m16n8k16.row.col.f32.f16.f16.f32 "
                    "{%0,%1,%2,%3}, {%4,%5,%6,%7}, {%8,%9}, {%0,%1,%2,%3};"
                    : "+f"(acc[f][nt][0]), "+f"(acc[f][nt][1]),
                      "+f"(acc[f][nt][2]), "+f"(acc[f][nt][3])
                    : "r"(a0), "r"(a1), "r"(a2), "r"(a3), "r"(b0), "r"(b1));
            }
        }
    }

    // epilogue
    __half* houts[4] = {o_xk, o_xv, o_xr, o_xg};
#pragma unroll
    for (int nt = 0; nt < 4; nt++) {
        int col = n0 + wn + nt * 8 + 2 * tig;
        float2 ma[5];
        ma[0] = *reinterpret_cast<const float2*>(m0p + col);
        ma[1] = *reinterpret_cast<const float2*>(m1p + col);
        ma[2] = *reinterpret_cast<const float2*>(m2p + col);
        ma[3] = *reinterpret_cast<const float2*>(m3p + col);
        ma[4] = *reinterpret_cast<const float2*>(m4p + col);
#pragma unroll
        for (int rr = 0; rr < 2; rr++) {
            int row = m0 + wm + gid + rr * 8;
            size_t base = (size_t)row * Cc + col;
            float2 xv  = *reinterpret_cast<const float2*>(x + base);
            float2 xxv = *reinterpret_cast<const float2*>(xx + base);
            {
                float d0 = acc[0][nt][rr * 2], d1 = acc[0][nt][rr * 2 + 1];
                float2 o;
                o.x = fmaf(xxv.x, ma[0].x + d0, xv.x);
                o.y = fmaf(xxv.y, ma[0].y + d1, xv.y);
                *reinterpret_cast<float2*>(o_xw + base) = o;
            }
#pragma unroll
            for (int f = 1; f < 5; f++) {
                float d0 = acc[f][nt][rr * 2], d1 = acc[f][nt][rr * 2 + 1];
                float v0 = fmaf(xxv.x, ma[f].x + d0, xv.x);
                float v1 = fmaf(xxv.y, ma[f].y + d1, xv.y);
                *reinterpret_cast<__half2*>(houts[f - 1] + base) = __floats2half2_rn(v0, v1);
            }
        }
    }
}

// ---------------------------------------------------------------------------
// WKV6 recurrence, j-split 2-way, depth-4 cp.async ring, 2 steps per barrier
// pair (round-11 proven version). grid = 256 blocks: (b, h, j-half, i-half).
// Stage layout (floats): [0:32) r, [32:64) k, [64:96) w, [96:128) v-half.
// ---------------------------------------------------------------------------
#define WKV_DEPTH 4
#define STG_F 128

__global__ __launch_bounds__(128)
void wkv_kernel(const float* __restrict__ rg, const float* __restrict__ kg,
                const float* __restrict__ vg, const float* __restrict__ wg,
                const float* __restrict__ u,
                float* __restrict__ ya, float* __restrict__ yb)
{
    int bid  = blockIdx.x;
    int ih   = bid & 1;
    int jh   = (bid >> 1) & 1;
    int h    = (bid >> 2) & 7;
    int b    = bid >> 5;
    int tid  = threadIdx.x;
    int lane = tid & 31;
    int warp = tid >> 5;

    __shared__ __align__(16) float stg[WKV_DEPTH][STG_F];
    __shared__ float part[2][4][32];

    float S[8];
#pragma unroll
    for (int jj = 0; jj < 8; jj++) S[jj] = 0.f;

    float uu[8];
#pragma unroll
    for (int jj = 0; jj < 8; jj++) uu[jj] = u[h * 64 + jh * 32 + warp * 8 + jj];

    const int hbase = h * 64;
    const int jbase = hbase + jh * 32;
    float* ydst = jh ? yb : ya;

    auto refill = [&](int slot, int tt) {
        if (tid < 32) {
            size_t gbase = (size_t)(b * Tc + tt) * Cc;
            const float* src;
            float* dst;
            if (tid < 8)       { src = rg + gbase + jbase + tid * 4;              dst = &stg[slot][tid * 4]; }
            else if (tid < 16) { src = kg + gbase + jbase + (tid - 8) * 4;        dst = &stg[slot][32 + (tid - 8) * 4]; }
            else if (tid < 24) { src = wg + gbase + jbase + (tid - 16) * 4;       dst = &stg[slot][64 + (tid - 16) * 4]; }
            else               { src = vg + gbase + hbase + ih * 32 + (tid - 24) * 4; dst = &stg[slot][96 + (tid - 24) * 4]; }
            uint32_t da = (uint32_t)__cvta_generic_to_shared(dst);
            asm volatile("cp.async.cg.shared.global [%0], [%1], 16;" :: "r"(da), "l"(src));
        }
        asm volatile("cp.async.commit_group;");
    };

    auto step = [&](const float* st, int pslot) {
        float vi = st[96 + lane];
        float y0 = 0.f, y1 = 0.f;
#pragma unroll
        for (int q = 0; q < 2; q++) {
            int j = warp * 8 + q * 4;
            float4 r4 = *reinterpret_cast<const float4*>(st + j);
            float4 k4 = *reinterpret_cast<const float4*>(st + 32 + j);
            float4 w4 = *reinterpret_cast<const float4*>(st + 64 + j);
            float kv, acc;
            kv = k4.x * vi; acc = fmaf(uu[q*4+0], kv, S[q*4+0]); y0 = fmaf(r4.x, acc, y0); S[q*4+0] = fmaf(w4.x, S[q*4+0], kv);
            kv = k4.y * vi; acc = fmaf(uu[q*4+1], kv, S[q*4+1]); y1 = fmaf(r4.y, acc, y1); S[q*4+1] = fmaf(w4.y, S[q*4+1], kv);
            kv = k4.z * vi; acc = fmaf(uu[q*4+2], kv, S[q*4+2]); y0 = fmaf(r4.z, acc, y0); S[q*4+2] = fmaf(w4.z, S[q*4+2], kv);
            kv = k4.w * vi; acc = fmaf(uu[q*4+3], kv, S[q*4+3]); y1 = fmaf(r4.w, acc, y1); S[q*4+3] = fmaf(w4.w, S[q*4+3], kv);
        }
        part[pslot][warp][lane] = y0 + y1;
    };

#pragma unroll
    for (int p = 0; p < WKV_DEPTH; p++) refill(p, p);
    asm volatile("cp.async.wait_group 2;");
    __syncthreads();

    for (int t = 0; t < Tc; t += 2) {
        int s0 = t & 3, s1 = (t + 1) & 3;
        step(&stg[s0][0], 0);
        step(&stg[s1][0], 1);
        __syncthreads();

        if (tid < 32) {
            size_t yo = (size_t)(b * Tc + t) * Cc + hbase + ih * 32 + tid;
            float pa = (part[0][0][tid] + part[0][1][tid]) + (part[0][2][tid] + part[0][3][tid]);
            float pb = (part[1][0][tid] + part[1][1][tid]) + (part[1][2][tid] + part[1][3][tid]);
            ydst[yo]      = pa;
            ydst[yo + Cc] = pb;
        }
        if (t + 4 < Tc) refill(s0, t + 4);
        else            asm volatile("cp.async.commit_group;");
        if (t + 5 < Tc) refill(s1, t + 5);
        else            asm volatile("cp.async.commit_group;");
        asm volatile("cp.async.wait_group 2;");
        __syncthreads();
    }
}

// ---------------------------------------------------------------------------
// GroupNorm + gate; combines WKV partials; writes fp16 z for the out GEMM.
// ---------------------------------------------------------------------------
__global__ __launch_bounds__(256)
void gn_kernel(const float* __restrict__ ya, const float* __restrict__ yb,
               const float* __restrict__ gsrc,
               const float* __restrict__ lng, const float* __restrict__ lnb,
               __half* __restrict__ hz)
{
    int warp = threadIdx.x >> 5, lane = threadIdx.x & 31;
    int grp = blockIdx.x * 8 + warp;
    int tg = grp >> 3, h = grp & 7;
    size_t base = (size_t)tg * Cc + h * 64;

    float y0 = ya[base + lane]      + yb[base + lane];
    float y1 = ya[base + 32 + lane] + yb[base + 32 + lane];
    float s  = y0 + y1;
    float ss = y0 * y0 + y1 * y1;
#pragma unroll
    for (int o = 16; o; o >>= 1) {
        s  += __shfl_xor_sync(0xffffffffu, s, o);
        ss += __shfl_xor_sync(0xffffffffu, ss, o);
    }
    float mean = s * (1.f / 64.f);
    float var  = ss * (1.f / 64.f) - mean * mean;
    float rstd = rsqrtf(var + 1e-5f);

    int c0 = h * 64 + lane;
    float z0 = fmaf((y0 - mean) * rstd, lng[c0],      lnb[c0]) * gsrc[base + lane];
    float z1 = fmaf((y1 - mean) * rstd, lng[c0 + 32], lnb[c0 + 32]) * gsrc[base + 32 + lane];
    hz[base + lane]      = __float2half(z0);
    hz[base + 32 + lane] = __float2half(z1);
}

// ---------------------------------------------------------------------------
// Launch
// ---------------------------------------------------------------------------
template <typename T>
static void* devptr_raw(T& sym)
{
    void* p = nullptr;
    cudaGetSymbolAddress(&p, sym);
    return p;
}

extern "C" void kernel_launch(void* const* d_in, const int* in_sizes, int n_in,
                              void* d_out, int out_size)
{
    const float* x      = (const float*)d_in[0];
    const float* maa_x  = (const float*)d_in[1];
    const float* maa_w  = (const float*)d_in[2];
    const float* maa_k  = (const float*)d_in[3];
    const float* maa_v  = (const float*)d_in[4];
    const float* maa_r  = (const float*)d_in[5];
    const float* maa_g  = (const float*)d_in[6];
    const float* W1     = (const float*)d_in[7];
    const float* W2     = (const float*)d_in[8];
    const float* tdec   = (const float*)d_in[9];
    const float* dw1    = (const float*)d_in[10];
    const float* dw2    = (const float*)d_in[11];
    const float* faaaa  = (const float*)d_in[12];
    const float* Wr     = (const float*)d_in[13];
    const float* Wk     = (const float*)d_in[14];
    const float* Wv     = (const float*)d_in[15];
    const float* Wg     = (const float*)d_in[16];
    const float* Wo     = (const float*)d_in[17];
    const float* ln_g   = (const float*)d_in[18];
    const float* ln_b   = (const float*)d_in[19];
    float* out = (float*)d_out;

    float*  p_xx   = (float*)devptr_raw(g_xx);
    float*  p_xxx  = (float*)devptr_raw(g_xxx);
    __half* p_h16  = (__half*)devptr_raw(g_h16);
    float*  p_xw   = (float*)devptr_raw(g_xw);
    float*  p_r    = (float*)devptr_raw(g_r);
    float*  p_k    = (float*)devptr_raw(g_k);
    float*  p_v    = (float*)devptr_raw(g_v);
    float*  p_gate = (float*)devptr_raw(g_gate);
    float*  p_wp   = (float*)devptr_raw(g_wp);
    float*  p_w    = (float*)devptr_raw(g_w);
    float*  p_y    = (float*)devptr_raw(g_y);
    float*  p_y2   = (float*)devptr_raw(g_y2);
    float*  p_w1t  = (float*)devptr_raw(g_w1t);
    float*  p_dw1t = (float*)devptr_raw(g_dw1t);
    float*  p_dw2t = (float*)devptr_raw(g_dw2t);
    __half* p_hxr  = (__half*)devptr_raw(g_hxr);
    __half* p_hxk  = (__half*)devptr_raw(g_hxk);
    __half* p_hxv  = (__half*)devptr_raw(g_hxv);
    __half* p_hxg  = (__half*)devptr_raw(g_hxg);
    __half* p_hz   = (__half*)devptr_raw(g_hz);
    __half* p_hWr  = (__half*)devptr_raw(g_hWr);
    __half* p_hWk  = (__half*)devptr_raw(g_hWk);
    __half* p_hWv  = (__half*)devptr_raw(g_hWv);
    __half* p_hWg  = (__half*)devptr_raw(g_hWg);
    __half* p_hWo  = (__half*)devptr_raw(g_hWo);
    __half* p_w2th = (__half*)devptr_raw(g_w2th);

    const int ewGrid = (BTC + 255) / 256;

    // 0) weight prep (tiny)
    transpose_pad<<<(256*512 + 128*512 + 512*64) / 256, 256>>>(
        W1, dw1, dw2, p_w1t, p_dw1t, p_dw2t);
    conv_weights_h<<<(Cc*Cc + 255) / 256, 256>>>(Wr, Wk, Wv, Wg, Wo, W2,
                                                 p_hWr, p_hWk, p_hWv, p_hWg, p_hWo,
                                                 p_w2th);

    // 1) token shift + xxx
    ew_shift_mix<<<ewGrid, 256>>>(x, maa_x, p_xx, p_xxx);

    // 2) h16 = fp16(tanh(xxx @ W1))   (tf32, epi 4)
    {
        dim3 grid(2, BT / 128);
        tf32_gemm<<<grid, 256>>>(p_xxx, p_w1t, (float*)p_h16, nullptr, BT, Cc, 160, 160, 4);
    }
    // 3) fused mix (fp16 tensor cores): xw fp32; xk/xv/xr/xg fp16
    {
        dim3 grid(Cc / 64, BT / 64);
        mix5h<<<grid, 256>>>(p_h16, p_w2th, maa_w, maa_k, maa_v, maa_r, maa_g,
                             x, p_xx, p_xw, p_hxk, p_hxv, p_hxr, p_hxg);
    }

    // 4) projections r, k, v, g  (fp16, batched single launch)
    {
        dim3 grid(Cc / 128, BT / 128, 4);
        proj4_h<<<grid, 256>>>(p_hxr, p_hxk, p_hxv, p_hxg,
                               p_hWr, p_hWk, p_hWv, p_hWg,
                               p_r, p_k, p_v, p_gate);
    }
    // 5) decay path (tf32): wp = tanh(xw @ dw1);  w = exp(-exp(tdec + wp @ dw2))
    {
        dim3 grid1(1, BT / 128);
        tf32_gemm<<<grid1, 256>>>(p_xw, p_dw1t, p_wp, nullptr, BT, Cc, 64, 64, 1);
        dim3 grid2(4, BT / 128);
        tf32_gemm<<<grid2, 256>>>(p_wp, p_dw2t, p_w, tdec, BT, 64, Cc, Cc, 3);
    }

    // 6) WKV6 recurrence (j-split 2-way, depth-4 ring)
    wkv_kernel<<<Bc * Hc * 4, 128>>>(p_r, p_k, p_v, p_w, faaaa, p_y, p_y2);

    // 7) GroupNorm + gate -> fp16 z
    gn_kernel<<<(BT * Hc) / 8, 256>>>(p_y, p_y2, p_gate, ln_g, ln_b, p_hz);

    // 8) out = z @ Wo^T  (fp16)
    {
        dim3 grid(Cc / 128, BT / 128);
        out_h<<<grid, 256>>>(p_hz, p_hWo, out);
    }
}